// round 13
// baseline (speedup 1.0000x reference)
#include <cuda_runtime.h>
#include <cuda_bf16.h>
#include <cuda_fp16.h>
#include <cstdint>

#define N_NODES   50000
#define N_PAD     50048          // 391 * 128
#define DEG       16
#define IN_F      256
#define OUT_C     256            // NUM_HEADS * OUT_FEATS
#define NUM_HEADS 4
#define OUT_F     64
#define NEG_SLOPE 0.2f

// ---------------- scratch (static device globals; no allocation) ------------
__device__ float  g_wt[(size_t)OUT_C * IN_F];           // W^T [n][k], tf32-rounded
__device__ __half g_hh[(size_t)N_PAD * OUT_C];          // projected features (fp16)
__device__ float  g_sl[(size_t)N_PAD * NUM_HEADS];      // dst scores (fp32)
__device__ float  g_sr[(size_t)N_PAD * NUM_HEADS];      // src scores (fp32)

__device__ __forceinline__ uint32_t smem_u32(const void* p) {
    uint32_t a;
    asm("{ .reg .u64 t; cvta.to.shared.u64 t, %1; cvt.u32.u64 %0, t; }" : "=r"(a) : "l"(p));
    return a;
}

__device__ __forceinline__ void ldsm_x4(uint32_t* f, uint32_t addr) {
    asm volatile("ldmatrix.sync.aligned.m8n8.x4.shared.b16 {%0,%1,%2,%3}, [%4];"
                 : "=r"(f[0]), "=r"(f[1]), "=r"(f[2]), "=r"(f[3]) : "r"(addr));
}

__device__ __forceinline__ void mma_tf32(float* c, const uint32_t* a,
                                         uint32_t b0, uint32_t b1) {
    asm volatile("mma.sync.aligned.m16n8k8.row.col.f32.tf32.tf32.f32 "
                 "{%0,%1,%2,%3}, {%4,%5,%6,%7}, {%8,%9}, {%0,%1,%2,%3};"
                 : "+f"(c[0]), "+f"(c[1]), "+f"(c[2]), "+f"(c[3])
                 : "r"(a[0]), "r"(a[1]), "r"(a[2]), "r"(a[3]), "r"(b0), "r"(b1));
}

__device__ __forceinline__ float to_tf32(float x) {
    uint32_t u;
    asm("cvt.rna.tf32.f32 %0, %1;" : "=r"(u) : "f"(x));
    return __uint_as_float(u);
}

// ---------------------------------------------------------------------------
// Kernel B: transpose W [k][n] -> g_wt [n][k], tf32-rounded (256KB, ~4us)
// ---------------------------------------------------------------------------
__global__ __launch_bounds__(256) void gat_transpose_w(const float* __restrict__ W)
{
    __shared__ float tile[32][33];
    const int bk = blockIdx.x * 32;
    const int bn = blockIdx.y * 32;
    const int tx = threadIdx.x & 31;
    const int ty = threadIdx.x >> 5;
    #pragma unroll
    for (int j = 0; j < 32; j += 8)
        tile[ty + j][tx] = W[(size_t)(bk + ty + j) * OUT_C + bn + tx];
    __syncthreads();
    #pragma unroll
    for (int j = 0; j < 32; j += 8)
        g_wt[(size_t)(bn + ty + j) * IN_F + bk + tx] = to_tf32(tile[tx][ty + j]);
}

// ---------------------------------------------------------------------------
// Kernel C: 1xTF32 mma.sync GEMM h = feat @ W, fp32 accum.
// CTA = 128(M) x 256(N), 512 threads, 16 warps 2(m) x 8(n); each warp keeps
// the PROVEN 64x32 tile / register layout from round 6. A is read exactly
// once (391 CTAs total). B tile = 256 x 32 (g_wt is 256KB, L2-resident).
// Dynamic smem 54KB (A 18KB + B 36KB), stride 36 f32 -> conflict-free ldsm.
// Epilogue: h stored FP16 + fused fp32 attn score dots for all 4 heads.
// ---------------------------------------------------------------------------
#define ASTR  36
#define A_E   (128 * ASTR)                 // 4608 f32
#define B_E   (256 * ASTR)                 // 9216 f32
#define DSMEM ((A_E + B_E) * 4)            // 55296 bytes

__global__ __launch_bounds__(512, 1) void gat_mma_kernel(
    const float* __restrict__ feat,
    const float* __restrict__ attn_l,
    const float* __restrict__ attn_r,
    int M)
{
    extern __shared__ __align__(16) float dsm[];
    float* const sA = dsm;                 // [128][36]
    float* const sB = dsm + A_E;           // [256][36]
    __shared__ float s_sl[128][4][2];      // [row][head][warp-pair]
    __shared__ float s_sr[128][4][2];

    const int tid  = threadIdx.x;
    const int wid  = tid >> 5;
    const int lane = tid & 31;
    const int bm   = blockIdx.x * 128;
    const int wm   = wid >> 3;             // 0..1
    const int wn   = wid & 7;              // 0..7

    const uint32_t sA_b = smem_u32(sA);
    const uint32_t sB_b = smem_u32(sB);

    float acc[4][4][4];
    #pragma unroll
    for (int mt = 0; mt < 4; mt++)
        #pragma unroll
        for (int nt = 0; nt < 4; nt++)
            #pragma unroll
            for (int r = 0; r < 4; r++) acc[mt][nt][r] = 0.f;

    // A loader: each thread owns a quarter-row (8 f32) of the 128x32 tile
    const int arow = tid >> 2;
    const int acol = (tid & 3) * 8;
    const bool arow_ok = (bm + arow) < M;
    const float* aptr = feat + (size_t)(bm + arow) * IN_F + acol;
    float* const sA_st = sA + arow * ASTR + acol;
    // B loader: each thread owns a half-row (16 f32) of the 256x32 tile
    const int brow = tid >> 1;
    const int bcol = (tid & 1) * 16;
    const float* bptr = g_wt + (size_t)brow * IN_F + bcol;
    float* const sB_st = sB + brow * ASTR + bcol;

    const int mi  = lane >> 3;
    const int aro = ((mi & 1) << 3) + (lane & 7);
    const int aco = (mi >> 1) << 2;
    const int bro = ((mi >> 1) << 3) + (lane & 7);
    const int bco = (mi & 1) << 2;

    for (int c = 0; c < 8; c++) {
        __syncthreads();
        {
            float4 a0, a1;
            if (arow_ok) {
                a0 = *reinterpret_cast<const float4*>(aptr + c * 32);
                a1 = *reinterpret_cast<const float4*>(aptr + c * 32 + 4);
            } else {
                a0 = a1 = make_float4(0.f, 0.f, 0.f, 0.f);
            }
            *reinterpret_cast<float4*>(sA_st)     = make_float4(to_tf32(a0.x), to_tf32(a0.y), to_tf32(a0.z), to_tf32(a0.w));
            *reinterpret_cast<float4*>(sA_st + 4) = make_float4(to_tf32(a1.x), to_tf32(a1.y), to_tf32(a1.z), to_tf32(a1.w));
            float4 b0 = *reinterpret_cast<const float4*>(bptr + c * 32);
            float4 b1 = *reinterpret_cast<const float4*>(bptr + c * 32 + 4);
            float4 b2 = *reinterpret_cast<const float4*>(bptr + c * 32 + 8);
            float4 b3 = *reinterpret_cast<const float4*>(bptr + c * 32 + 12);
            *reinterpret_cast<float4*>(sB_st)      = b0;   // pre-rounded tf32
            *reinterpret_cast<float4*>(sB_st + 4)  = b1;
            *reinterpret_cast<float4*>(sB_st + 8)  = b2;
            *reinterpret_cast<float4*>(sB_st + 12) = b3;
        }
        __syncthreads();

        #pragma unroll
        for (int ks = 0; ks < 4; ks++) {
            uint32_t af[4][4];
            uint32_t bf[2][4];
            #pragma unroll
            for (int bp = 0; bp < 2; bp++) {
                int r = wn * 32 + bp * 16 + bro;
                uint32_t off = (uint32_t)(r * ASTR + ks * 8 + bco) * 4;
                ldsm_x4(bf[bp], sB_b + off);
            }
            #pragma unroll
            for (int mt = 0; mt < 4; mt++) {
                int r = wm * 64 + mt * 16 + aro;
                uint32_t off = (uint32_t)(r * ASTR + ks * 8 + aco) * 4;
                ldsm_x4(af[mt], sA_b + off);
            }
            #pragma unroll
            for (int mt = 0; mt < 4; mt++)
                #pragma unroll
                for (int nt = 0; nt < 4; nt++)
                    mma_tf32(acc[mt][nt], af[mt],
                             bf[nt >> 1][(nt & 1) * 2],
                             bf[nt >> 1][(nt & 1) * 2 + 1]);
        }
    }

    // ---- epilogue: store h as fp16 + fused fp32 score dots ------------------
    const int hdl = wn >> 1;               // head 0..3 (warp's 32 cols in 1 head)
    const int wp  = wn & 1;

    float alv[4][2], arv[4][2];
    #pragma unroll
    for (int nt = 0; nt < 4; nt++) {
        int col = wn * 32 + nt * 8 + (lane & 3) * 2;
        alv[nt][0] = attn_l[col];     alv[nt][1] = attn_l[col + 1];
        arv[nt][0] = attn_r[col];     arv[nt][1] = attn_r[col + 1];
    }

    #pragma unroll
    for (int mt = 0; mt < 4; mt++) {
        int r0 = wm * 64 + mt * 16 + (lane >> 2);
        int r8 = r0 + 8;
        float sl0 = 0.f, sl8 = 0.f, sr0 = 0.f, sr8 = 0.f;
        #pragma unroll
        for (int nt = 0; nt < 4; nt++) {
            int col = wn * 32 + nt * 8 + (lane & 3) * 2;
            float2 v0 = make_float2(acc[mt][nt][0], acc[mt][nt][1]);
            float2 v8 = make_float2(acc[mt][nt][2], acc[mt][nt][3]);
            __half2 p0 = __floats2half2_rn(v0.x, v0.y);
            __half2 p8 = __floats2half2_rn(v8.x, v8.y);
            *reinterpret_cast<__half2*>(&g_hh[(size_t)(bm + r0) * OUT_C + col]) = p0;
            *reinterpret_cast<__half2*>(&g_hh[(size_t)(bm + r8) * OUT_C + col]) = p8;
            sl0 += alv[nt][0] * v0.x + alv[nt][1] * v0.y;
            sl8 += alv[nt][0] * v8.x + alv[nt][1] * v8.y;
            sr0 += arv[nt][0] * v0.x + arv[nt][1] * v0.y;
            sr8 += arv[nt][0] * v8.x + arv[nt][1] * v8.y;
        }
        #pragma unroll
        for (int off = 1; off < 4; off <<= 1) {
            sl0 += __shfl_xor_sync(0xffffffffu, sl0, off);
            sl8 += __shfl_xor_sync(0xffffffffu, sl8, off);
            sr0 += __shfl_xor_sync(0xffffffffu, sr0, off);
            sr8 += __shfl_xor_sync(0xffffffffu, sr8, off);
        }
        if ((lane & 3) == 0) {
            s_sl[r0][hdl][wp] = sl0;  s_sl[r8][hdl][wp] = sl8;
            s_sr[r0][hdl][wp] = sr0;  s_sr[r8][hdl][wp] = sr8;
        }
    }
    __syncthreads();

    if (tid < 128) {
        int gr = bm + tid;
        float4 l = make_float4(s_sl[tid][0][0] + s_sl[tid][0][1],
                               s_sl[tid][1][0] + s_sl[tid][1][1],
                               s_sl[tid][2][0] + s_sl[tid][2][1],
                               s_sl[tid][3][0] + s_sl[tid][3][1]);
        float4 r = make_float4(s_sr[tid][0][0] + s_sr[tid][0][1],
                               s_sr[tid][1][0] + s_sr[tid][1][1],
                               s_sr[tid][2][0] + s_sr[tid][2][1],
                               s_sr[tid][3][0] + s_sr[tid][3][1]);
        *reinterpret_cast<float4*>(&g_sl[(size_t)gr * 4]) = l;
        *reinterpret_cast<float4*>(&g_sr[(size_t)gr * 4]) = r;
    }
}

// ---------------------------------------------------------------------------
// Kernel D (round-11 proven): softmax + fp16-gather aggregation.
// 64 threads per node, 4 nodes per block; thread t gathers 4 halves (LDG.64).
// ---------------------------------------------------------------------------
__global__ __launch_bounds__(256) void gat_agg_kernel(
    const int*    __restrict__ col_ind,
    const uint2*  __restrict__ hh2,
    const float4* __restrict__ sl4,
    const float4* __restrict__ sr4,
    float4*       __restrict__ out4)
{
    const int local = threadIdx.x >> 6;
    const int t     = threadIdx.x & 63;
    const int n     = blockIdx.x * 4 + local;

    __shared__ int   ssrc  [4][16];
    __shared__ float salpha[4][16][4];

    if (t < 16) {
        int s = col_ind[n * DEG + t];
        ssrc[local][t] = s;
        float4 l = sl4[n];
        float4 r = sr4[s];
        float e0 = l.x + r.x, e1 = l.y + r.y, e2 = l.z + r.z, e3 = l.w + r.w;
        e0 = (e0 > 0.f) ? e0 : NEG_SLOPE * e0;
        e1 = (e1 > 0.f) ? e1 : NEG_SLOPE * e1;
        e2 = (e2 > 0.f) ? e2 : NEG_SLOPE * e2;
        e3 = (e3 > 0.f) ? e3 : NEG_SLOPE * e3;
        float m0 = e0, m1 = e1, m2 = e2, m3 = e3;
        #pragma unroll
        for (int off = 8; off > 0; off >>= 1) {
            m0 = fmaxf(m0, __shfl_xor_sync(0xffffu, m0, off));
            m1 = fmaxf(m1, __shfl_xor_sync(0xffffu, m1, off));
            m2 = fmaxf(m2, __shfl_xor_sync(0xffffu, m2, off));
            m3 = fmaxf(m3, __shfl_xor_sync(0xffffu, m3, off));
        }
        float x0 = __expf(e0 - m0), x1 = __expf(e1 - m1);
        float x2 = __expf(e2 - m2), x3 = __expf(e3 - m3);
        float s0 = x0, s1 = x1, s2 = x2, s3 = x3;
        #pragma unroll
        for (int off = 8; off > 0; off >>= 1) {
            s0 += __shfl_xor_sync(0xffffu, s0, off);
            s1 += __shfl_xor_sync(0xffffu, s1, off);
            s2 += __shfl_xor_sync(0xffffu, s2, off);
            s3 += __shfl_xor_sync(0xffffu, s3, off);
        }
        *reinterpret_cast<float4*>(&salpha[local][t][0]) =
            make_float4(x0 / s0, x1 / s1, x2 / s2, x3 / s3);
    }
    __syncthreads();

    const int hd = t >> 4;
    float4 acc = make_float4(0.f, 0.f, 0.f, 0.f);
    #pragma unroll
    for (int k = 0; k < DEG; k++) {
        float a  = salpha[local][k][hd];
        uint2 u  = hh2[(size_t)ssrc[local][k] * 64 + t];
        float2 f01 = __half22float2(*reinterpret_cast<__half2*>(&u.x));
        float2 f23 = __half22float2(*reinterpret_cast<__half2*>(&u.y));
        acc.x += a * f01.x;
        acc.y += a * f01.y;
        acc.z += a * f23.x;
        acc.w += a * f23.y;
    }
    out4[(size_t)n * 64 + t] = acc;
}

// ---------------------------------------------------------------------------
// Launch. Inputs: row_ptr, col_ind, col_ptr, row_ind, feat, W, attn_l, attn_r
// ---------------------------------------------------------------------------
extern "C" void kernel_launch(void* const* d_in, const int* in_sizes, int n_in,
                              void* d_out, int out_size)
{
    const int*   col_ind = (const int*)  d_in[1];
    const float* feat    = (const float*)d_in[4];
    const float* W       = (const float*)d_in[5];
    const float* attn_l  = (const float*)d_in[6];
    const float* attn_r  = (const float*)d_in[7];
    float*       out     = (float*)      d_out;

    const int M = in_sizes[4] / IN_F;    // 50000

    __half* hh_ptr = nullptr;
    float  *sl_ptr = nullptr, *sr_ptr = nullptr;
    cudaGetSymbolAddress((void**)&hh_ptr, g_hh);
    cudaGetSymbolAddress((void**)&sl_ptr, g_sl);
    cudaGetSymbolAddress((void**)&sr_ptr, g_sr);

    cudaFuncSetAttribute(gat_mma_kernel,
                         cudaFuncAttributeMaxDynamicSharedMemorySize, DSMEM);

    dim3 gtw(IN_F / 32, OUT_C / 32);
    gat_transpose_w<<<gtw, 256>>>(W);

    gat_mma_kernel<<<N_PAD / 128, 512, DSMEM>>>(feat, attn_l, attn_r, M);

    gat_agg_kernel<<<M / 4, 256>>>(col_ind,
                                   (const uint2*)hh_ptr,
                                   (const float4*)sl_ptr,
                                   (const float4*)sr_ptr,
                                   (float4*)out);
}

// round 14
// speedup vs baseline: 1.0735x; 1.0735x over previous
#include <cuda_runtime.h>
#include <cuda_bf16.h>
#include <cuda_fp16.h>
#include <cstdint>

#define N_NODES   50000
#define N_PAD     50048          // 391 * 128
#define DEG       16
#define IN_F      256
#define OUT_C     256            // NUM_HEADS * OUT_FEATS
#define NUM_HEADS 4
#define OUT_F     64
#define NEG_SLOPE 0.2f

// ---------------- scratch (static device globals; no allocation) ------------
__device__ float  g_wt[(size_t)OUT_C * IN_F];           // W^T [n][k], tf32-rounded
__device__ __half g_hh[(size_t)N_PAD * OUT_C];          // projected features (fp16)
__device__ float  g_sl[(size_t)N_PAD * NUM_HEADS];      // dst scores (fp32)
__device__ float  g_sr[(size_t)N_PAD * NUM_HEADS];      // src scores (fp32)

__device__ __forceinline__ uint32_t smem_u32(const void* p) {
    uint32_t a;
    asm("{ .reg .u64 t; cvta.to.shared.u64 t, %1; cvt.u32.u64 %0, t; }" : "=r"(a) : "l"(p));
    return a;
}

__device__ __forceinline__ void ldsm_x4(uint32_t* f, uint32_t addr) {
    asm volatile("ldmatrix.sync.aligned.m8n8.x4.shared.b16 {%0,%1,%2,%3}, [%4];"
                 : "=r"(f[0]), "=r"(f[1]), "=r"(f[2]), "=r"(f[3]) : "r"(addr));
}

__device__ __forceinline__ void mma_tf32(float* c, const uint32_t* a,
                                         uint32_t b0, uint32_t b1) {
    asm volatile("mma.sync.aligned.m16n8k8.row.col.f32.tf32.tf32.f32 "
                 "{%0,%1,%2,%3}, {%4,%5,%6,%7}, {%8,%9}, {%0,%1,%2,%3};"
                 : "+f"(c[0]), "+f"(c[1]), "+f"(c[2]), "+f"(c[3])
                 : "r"(a[0]), "r"(a[1]), "r"(a[2]), "r"(a[3]), "r"(b0), "r"(b1));
}

__device__ __forceinline__ float to_tf32(float x) {
    uint32_t u;
    asm("cvt.rna.tf32.f32 %0, %1;" : "=r"(u) : "f"(x));
    return __uint_as_float(u);
}

// ---------------------------------------------------------------------------
// Kernel B: transpose W [k][n] -> g_wt [n][k], tf32-rounded (256KB, ~4us)
// ---------------------------------------------------------------------------
__global__ __launch_bounds__(256) void gat_transpose_w(const float* __restrict__ W)
{
    __shared__ float tile[32][33];
    const int bk = blockIdx.x * 32;
    const int bn = blockIdx.y * 32;
    const int tx = threadIdx.x & 31;
    const int ty = threadIdx.x >> 5;
    #pragma unroll
    for (int j = 0; j < 32; j += 8)
        tile[ty + j][tx] = W[(size_t)(bk + ty + j) * OUT_C + bn + tx];
    __syncthreads();
    #pragma unroll
    for (int j = 0; j < 32; j += 8)
        g_wt[(size_t)(bn + ty + j) * IN_F + bk + tx] = to_tf32(tile[tx][ty + j]);
}

// ---------------------------------------------------------------------------
// Kernel C (round-6 proven mainloop): 1xTF32 mma.sync GEMM h = feat @ W.
// ONLY change vs the 112.3us winner: grid is (2, 391) with bn = blockIdx.x,
// so the two CTAs sharing an A strip are launch-adjacent (same wave) and the
// second A read hits L2 instead of streaming 51MB from DRAM again.
// CTA = 128(M) x 128(N); 8 warps 2(m) x 4(n); k-chunk 32; 2 CTAs/SM.
// Epilogue: h stored as FP16 + fused fp32 attn score dots.
// ---------------------------------------------------------------------------
#define ASTR 36

__global__ __launch_bounds__(256, 2) void gat_mma_kernel(
    const float* __restrict__ feat,
    const float* __restrict__ attn_l,
    const float* __restrict__ attn_r,
    int M)
{
    __shared__ __align__(16) float sA[128 * ASTR];
    __shared__ __align__(16) float sB[128 * ASTR];
    __shared__ float s_sl[128][2][2];
    __shared__ float s_sr[128][2][2];

    const int tid  = threadIdx.x;
    const int wid  = tid >> 5;
    const int lane = tid & 31;
    const int bm   = blockIdx.y * 128;     // bn varies fastest across CTAs
    const int bn   = blockIdx.x * 128;
    const int wm   = wid >> 2;
    const int wn   = wid & 3;

    const uint32_t sA_b = smem_u32(sA);
    const uint32_t sB_b = smem_u32(sB);

    float acc[4][4][4];
    #pragma unroll
    for (int mt = 0; mt < 4; mt++)
        #pragma unroll
        for (int nt = 0; nt < 4; nt++)
            #pragma unroll
            for (int r = 0; r < 4; r++) acc[mt][nt][r] = 0.f;

    const int lrow = tid >> 1;
    const int lcol = (tid & 1) * 16;
    const bool arow_ok = (bm + lrow) < M;
    const float* aptr = feat + (size_t)(bm + lrow) * IN_F + lcol;
    const float* bptr = g_wt + (size_t)(bn + lrow) * IN_F + lcol;
    float* const sA_st = sA + lrow * ASTR + lcol;
    float* const sB_st = sB + lrow * ASTR + lcol;

    const int mi  = lane >> 3;
    const int aro = ((mi & 1) << 3) + (lane & 7);
    const int aco = (mi >> 1) << 2;
    const int bro = ((mi >> 1) << 3) + (lane & 7);
    const int bco = (mi & 1) << 2;

    for (int c = 0; c < 8; c++) {
        __syncthreads();
        {
            float4 a0, a1, a2, a3;
            if (arow_ok) {
                a0 = *reinterpret_cast<const float4*>(aptr + c * 32);
                a1 = *reinterpret_cast<const float4*>(aptr + c * 32 + 4);
                a2 = *reinterpret_cast<const float4*>(aptr + c * 32 + 8);
                a3 = *reinterpret_cast<const float4*>(aptr + c * 32 + 12);
            } else {
                a0 = a1 = a2 = a3 = make_float4(0.f, 0.f, 0.f, 0.f);
            }
            float4 b0 = *reinterpret_cast<const float4*>(bptr + c * 32);
            float4 b1 = *reinterpret_cast<const float4*>(bptr + c * 32 + 4);
            float4 b2 = *reinterpret_cast<const float4*>(bptr + c * 32 + 8);
            float4 b3 = *reinterpret_cast<const float4*>(bptr + c * 32 + 12);
            *reinterpret_cast<float4*>(sA_st)      = make_float4(to_tf32(a0.x), to_tf32(a0.y), to_tf32(a0.z), to_tf32(a0.w));
            *reinterpret_cast<float4*>(sA_st + 4)  = make_float4(to_tf32(a1.x), to_tf32(a1.y), to_tf32(a1.z), to_tf32(a1.w));
            *reinterpret_cast<float4*>(sA_st + 8)  = make_float4(to_tf32(a2.x), to_tf32(a2.y), to_tf32(a2.z), to_tf32(a2.w));
            *reinterpret_cast<float4*>(sA_st + 12) = make_float4(to_tf32(a3.x), to_tf32(a3.y), to_tf32(a3.z), to_tf32(a3.w));
            *reinterpret_cast<float4*>(sB_st)      = b0;
            *reinterpret_cast<float4*>(sB_st + 4)  = b1;
            *reinterpret_cast<float4*>(sB_st + 8)  = b2;
            *reinterpret_cast<float4*>(sB_st + 12) = b3;
        }
        __syncthreads();

        #pragma unroll
        for (int ks = 0; ks < 4; ks++) {
            uint32_t af[4][4];
            uint32_t bf[2][4];
            #pragma unroll
            for (int bp = 0; bp < 2; bp++) {
                int r = wn * 32 + bp * 16 + bro;
                uint32_t off = (uint32_t)(r * ASTR + ks * 8 + bco) * 4;
                ldsm_x4(bf[bp], sB_b + off);
            }
            #pragma unroll
            for (int mt = 0; mt < 4; mt++) {
                int r = wm * 64 + mt * 16 + aro;
                uint32_t off = (uint32_t)(r * ASTR + ks * 8 + aco) * 4;
                ldsm_x4(af[mt], sA_b + off);
            }
            #pragma unroll
            for (int mt = 0; mt < 4; mt++)
                #pragma unroll
                for (int nt = 0; nt < 4; nt++)
                    mma_tf32(acc[mt][nt], af[mt],
                             bf[nt >> 1][(nt & 1) * 2],
                             bf[nt >> 1][(nt & 1) * 2 + 1]);
        }
    }

    // ---- epilogue: store h as fp16 + fused fp32 score dots ------------------
    const int hdl = wn >> 1;
    const int wp  = wn & 1;

    float alv[4][2], arv[4][2];
    #pragma unroll
    for (int nt = 0; nt < 4; nt++) {
        int col = bn + wn * 32 + nt * 8 + (lane & 3) * 2;
        alv[nt][0] = attn_l[col];     alv[nt][1] = attn_l[col + 1];
        arv[nt][0] = attn_r[col];     arv[nt][1] = attn_r[col + 1];
    }

    #pragma unroll
    for (int mt = 0; mt < 4; mt++) {
        int r0 = wm * 64 + mt * 16 + (lane >> 2);
        int r8 = r0 + 8;
        float sl0 = 0.f, sl8 = 0.f, sr0 = 0.f, sr8 = 0.f;
        #pragma unroll
        for (int nt = 0; nt < 4; nt++) {
            int col = bn + wn * 32 + nt * 8 + (lane & 3) * 2;
            float2 v0 = make_float2(acc[mt][nt][0], acc[mt][nt][1]);
            float2 v8 = make_float2(acc[mt][nt][2], acc[mt][nt][3]);
            __half2 p0 = __floats2half2_rn(v0.x, v0.y);
            __half2 p8 = __floats2half2_rn(v8.x, v8.y);
            *reinterpret_cast<__half2*>(&g_hh[(size_t)(bm + r0) * OUT_C + col]) = p0;
            *reinterpret_cast<__half2*>(&g_hh[(size_t)(bm + r8) * OUT_C + col]) = p8;
            sl0 += alv[nt][0] * v0.x + alv[nt][1] * v0.y;
            sl8 += alv[nt][0] * v8.x + alv[nt][1] * v8.y;
            sr0 += arv[nt][0] * v0.x + arv[nt][1] * v0.y;
            sr8 += arv[nt][0] * v8.x + arv[nt][1] * v8.y;
        }
        #pragma unroll
        for (int off = 1; off < 4; off <<= 1) {
            sl0 += __shfl_xor_sync(0xffffffffu, sl0, off);
            sl8 += __shfl_xor_sync(0xffffffffu, sl8, off);
            sr0 += __shfl_xor_sync(0xffffffffu, sr0, off);
            sr8 += __shfl_xor_sync(0xffffffffu, sr8, off);
        }
        if ((lane & 3) == 0) {
            s_sl[r0][hdl][wp] = sl0;  s_sl[r8][hdl][wp] = sl8;
            s_sr[r0][hdl][wp] = sr0;  s_sr[r8][hdl][wp] = sr8;
        }
    }
    __syncthreads();

    if (tid < 128) {
        int gr = bm + tid;
        int hb = bn >> 6;
        g_sl[(size_t)gr * 4 + hb + 0] = s_sl[tid][0][0] + s_sl[tid][0][1];
        g_sl[(size_t)gr * 4 + hb + 1] = s_sl[tid][1][0] + s_sl[tid][1][1];
        g_sr[(size_t)gr * 4 + hb + 0] = s_sr[tid][0][0] + s_sr[tid][0][1];
        g_sr[(size_t)gr * 4 + hb + 1] = s_sr[tid][1][0] + s_sr[tid][1][1];
    }
}

// ---------------------------------------------------------------------------
// Kernel D (round-11 proven, 112.3us config): softmax + fp16-gather agg.
// 64 threads per node, 4 nodes per block; thread t gathers 4 halves (LDG.64).
// ---------------------------------------------------------------------------
__global__ __launch_bounds__(256) void gat_agg_kernel(
    const int*    __restrict__ col_ind,
    const uint2*  __restrict__ hh2,
    const float4* __restrict__ sl4,
    const float4* __restrict__ sr4,
    float4*       __restrict__ out4)
{
    const int local = threadIdx.x >> 6;
    const int t     = threadIdx.x & 63;
    const int n     = blockIdx.x * 4 + local;

    __shared__ int   ssrc  [4][16];
    __shared__ float salpha[4][16][4];

    if (t < 16) {
        int s = col_ind[n * DEG + t];
        ssrc[local][t] = s;
        float4 l = sl4[n];
        float4 r = sr4[s];
        float e0 = l.x + r.x, e1 = l.y + r.y, e2 = l.z + r.z, e3 = l.w + r.w;
        e0 = (e0 > 0.f) ? e0 : NEG_SLOPE * e0;
        e1 = (e1 > 0.f) ? e1 : NEG_SLOPE * e1;
        e2 = (e2 > 0.f) ? e2 : NEG_SLOPE * e2;
        e3 = (e3 > 0.f) ? e3 : NEG_SLOPE * e3;
        float m0 = e0, m1 = e1, m2 = e2, m3 = e3;
        #pragma unroll
        for (int off = 8; off > 0; off >>= 1) {
            m0 = fmaxf(m0, __shfl_xor_sync(0xffffu, m0, off));
            m1 = fmaxf(m1, __shfl_xor_sync(0xffffu, m1, off));
            m2 = fmaxf(m2, __shfl_xor_sync(0xffffu, m2, off));
            m3 = fmaxf(m3, __shfl_xor_sync(0xffffu, m3, off));
        }
        float x0 = __expf(e0 - m0), x1 = __expf(e1 - m1);
        float x2 = __expf(e2 - m2), x3 = __expf(e3 - m3);
        float s0 = x0, s1 = x1, s2 = x2, s3 = x3;
        #pragma unroll
        for (int off = 8; off > 0; off >>= 1) {
            s0 += __shfl_xor_sync(0xffffu, s0, off);
            s1 += __shfl_xor_sync(0xffffu, s1, off);
            s2 += __shfl_xor_sync(0xffffu, s2, off);
            s3 += __shfl_xor_sync(0xffffu, s3, off);
        }
        *reinterpret_cast<float4*>(&salpha[local][t][0]) =
            make_float4(x0 / s0, x1 / s1, x2 / s2, x3 / s3);
    }
    __syncthreads();

    const int hd = t >> 4;
    float4 acc = make_float4(0.f, 0.f, 0.f, 0.f);
    #pragma unroll
    for (int k = 0; k < DEG; k++) {
        float a  = salpha[local][k][hd];
        uint2 u  = hh2[(size_t)ssrc[local][k] * 64 + t];
        float2 f01 = __half22float2(*reinterpret_cast<__half2*>(&u.x));
        float2 f23 = __half22float2(*reinterpret_cast<__half2*>(&u.y));
        acc.x += a * f01.x;
        acc.y += a * f01.y;
        acc.z += a * f23.x;
        acc.w += a * f23.y;
    }
    out4[(size_t)n * 64 + t] = acc;
}

// ---------------------------------------------------------------------------
// Launch. Inputs: row_ptr, col_ind, col_ptr, row_ind, feat, W, attn_l, attn_r
// ---------------------------------------------------------------------------
extern "C" void kernel_launch(void* const* d_in, const int* in_sizes, int n_in,
                              void* d_out, int out_size)
{
    const int*   col_ind = (const int*)  d_in[1];
    const float* feat    = (const float*)d_in[4];
    const float* W       = (const float*)d_in[5];
    const float* attn_l  = (const float*)d_in[6];
    const float* attn_r  = (const float*)d_in[7];
    float*       out     = (float*)      d_out;

    const int M = in_sizes[4] / IN_F;    // 50000

    __half* hh_ptr = nullptr;
    float  *sl_ptr = nullptr, *sr_ptr = nullptr;
    cudaGetSymbolAddress((void**)&hh_ptr, g_hh);
    cudaGetSymbolAddress((void**)&sl_ptr, g_sl);
    cudaGetSymbolAddress((void**)&sr_ptr, g_sr);

    dim3 gtw(IN_F / 32, OUT_C / 32);
    gat_transpose_w<<<gtw, 256>>>(W);

    dim3 gmm(2, N_PAD / 128);            // bn fastest: A-strip pairs adjacent
    gat_mma_kernel<<<gmm, 256>>>(feat, attn_l, attn_r, M);

    gat_agg_kernel<<<M / 4, 256>>>(col_ind,
                                   (const uint2*)hh_ptr,
                                   (const float4*)sl_ptr,
                                   (const float4*)sr_ptr,
                                   (float4*)out);
}

// round 15
// speedup vs baseline: 1.2264x; 1.1424x over previous
#include <cuda_runtime.h>
#include <cuda_bf16.h>
#include <cuda_fp16.h>
#include <cstdint>

#define N_NODES   50000
#define N_PAD     50048          // 391 * 128
#define DEG       16
#define IN_F      256
#define OUT_C     256            // NUM_HEADS * OUT_FEATS
#define NUM_HEADS 4
#define OUT_F     64
#define NEG_SLOPE 0.2f

// ---------------- scratch (static device globals; no allocation) ------------
__device__ __half g_wh[(size_t)OUT_C * IN_F];           // W^T [n][k], fp16
__device__ __half g_hh[(size_t)N_PAD * OUT_C];          // projected features (fp16)
__device__ float  g_sl[(size_t)N_PAD * NUM_HEADS];      // dst scores (fp32)
__device__ float  g_sr[(size_t)N_PAD * NUM_HEADS];      // src scores (fp32)

__device__ __forceinline__ uint32_t smem_u32(const void* p) {
    uint32_t a;
    asm("{ .reg .u64 t; cvta.to.shared.u64 t, %1; cvt.u32.u64 %0, t; }" : "=r"(a) : "l"(p));
    return a;
}

__device__ __forceinline__ void ldsm_x4(uint32_t* f, uint32_t addr) {
    asm volatile("ldmatrix.sync.aligned.m8n8.x4.shared.b16 {%0,%1,%2,%3}, [%4];"
                 : "=r"(f[0]), "=r"(f[1]), "=r"(f[2]), "=r"(f[3]) : "r"(addr));
}

__device__ __forceinline__ void mma_f16(float* c, const uint32_t* a,
                                        uint32_t b0, uint32_t b1) {
    asm volatile("mma.sync.aligned.m16n8k16.row.col.f32.f16.f16.f32 "
                 "{%0,%1,%2,%3}, {%4,%5,%6,%7}, {%8,%9}, {%0,%1,%2,%3};"
                 : "+f"(c[0]), "+f"(c[1]), "+f"(c[2]), "+f"(c[3])
                 : "r"(a[0]), "r"(a[1]), "r"(a[2]), "r"(a[3]), "r"(b0), "r"(b1));
}

// pack two fp32 -> fp16x2
__device__ __forceinline__ uint32_t pk2h(float x, float y) {
    __half2 h = __floats2half2_rn(x, y);
    return *reinterpret_cast<uint32_t*>(&h);
}

// ---------------------------------------------------------------------------
// Kernel B: transpose W [k][n] -> g_wh [n][k], fp16 (~4us)
// ---------------------------------------------------------------------------
__global__ __launch_bounds__(256) void gat_transpose_w(const float* __restrict__ W)
{
    __shared__ float tile[32][33];
    const int bk = blockIdx.x * 32;
    const int bn = blockIdx.y * 32;
    const int tx = threadIdx.x & 31;
    const int ty = threadIdx.x >> 5;
    #pragma unroll
    for (int j = 0; j < 32; j += 8)
        tile[ty + j][tx] = W[(size_t)(bk + ty + j) * OUT_C + bn + tx];
    __syncthreads();
    #pragma unroll
    for (int j = 0; j < 32; j += 8)
        g_wh[(size_t)(bn + ty + j) * IN_F + bk + tx] = __float2half_rn(tile[tx][ty + j]);
}

// ---------------------------------------------------------------------------
// Kernel C: single-pass FP16 mma.sync GEMM h = feat @ W, fp32 accum.
// Round-4 PROVEN structure (TSTR=40 smem, identical ldmatrix/fragment layout)
// minus the 3-pass split: one A tile + one B tile, kind f16.
// CTA = 128(M) x 128(N); 8 warps 2(m) x 4(n); warp tile 64x32; k-chunk 32.
// A converted fp32 -> fp16 in loader registers. 2 CTAs/SM (20KB smem).
// Epilogue: h stored FP16 + fused fp32 attn score dots (proven verbatim).
// ---------------------------------------------------------------------------
#define TSTR 40   // smem row stride in fp16 elems (80B) -> conflict-free ldsm

__global__ __launch_bounds__(256, 2) void gat_mma_kernel(
    const float* __restrict__ feat,
    const float* __restrict__ attn_l,
    const float* __restrict__ attn_r,
    int M)
{
    __shared__ __align__(16) __half sA[128 * TSTR];
    __shared__ __align__(16) __half sB[128 * TSTR];
    __shared__ float s_sl[128][2][2];
    __shared__ float s_sr[128][2][2];

    const int tid  = threadIdx.x;
    const int wid  = tid >> 5;
    const int lane = tid & 31;
    const int bm   = blockIdx.x * 128;
    const int bn   = blockIdx.y * 128;
    const int wm   = wid >> 2;
    const int wn   = wid & 3;

    const uint32_t sA_b = smem_u32(sA);
    const uint32_t sB_b = smem_u32(sB);

    float acc[4][4][4];
    #pragma unroll
    for (int mt = 0; mt < 4; mt++)
        #pragma unroll
        for (int nt = 0; nt < 4; nt++)
            #pragma unroll
            for (int r = 0; r < 4; r++) acc[mt][nt][r] = 0.f;

    // loader: each thread owns one half-row (16 elems) of the 128x32 tile
    const int lrow = tid >> 1;
    const int lcol = (tid & 1) * 16;
    const bool arow_ok = (bm + lrow) < M;
    const float*  aptr = feat + (size_t)(bm + lrow) * IN_F + lcol;
    const __half* bptr = g_wh + (size_t)(bn + lrow) * IN_F + lcol;
    __half* const sA_st = sA + lrow * TSTR + lcol;
    __half* const sB_st = sB + lrow * TSTR + lcol;

    // ldmatrix lane-address components (proven in round 4, b16 tiles)
    const int mi  = lane >> 3;
    const int aro = ((mi & 1) << 3) + (lane & 7);    // A: row within m16
    const int aco = (mi >> 1) << 3;                  // A: k offset (halves)
    const int bro = ((mi >> 1) << 3) + (lane & 7);   // B: n within n16
    const int bco = (mi & 1) << 3;                   // B: k offset

    for (int c = 0; c < 8; c++) {                    // k-chunks of 32
        __syncthreads();
        {
            float4 a0, a1, a2, a3;
            if (arow_ok) {
                a0 = *reinterpret_cast<const float4*>(aptr + c * 32);
                a1 = *reinterpret_cast<const float4*>(aptr + c * 32 + 4);
                a2 = *reinterpret_cast<const float4*>(aptr + c * 32 + 8);
                a3 = *reinterpret_cast<const float4*>(aptr + c * 32 + 12);
            } else {
                a0 = a1 = a2 = a3 = make_float4(0.f, 0.f, 0.f, 0.f);
            }
            uint4 b0 = *reinterpret_cast<const uint4*>(bptr + c * 32);      // 8 halves
            uint4 b1 = *reinterpret_cast<const uint4*>(bptr + c * 32 + 8);  // 8 halves
            uint4 av0 = make_uint4(pk2h(a0.x, a0.y), pk2h(a0.z, a0.w),
                                   pk2h(a1.x, a1.y), pk2h(a1.z, a1.w));
            uint4 av1 = make_uint4(pk2h(a2.x, a2.y), pk2h(a2.z, a2.w),
                                   pk2h(a3.x, a3.y), pk2h(a3.z, a3.w));
            *reinterpret_cast<uint4*>(sA_st)     = av0;
            *reinterpret_cast<uint4*>(sA_st + 8) = av1;
            *reinterpret_cast<uint4*>(sB_st)     = b0;
            *reinterpret_cast<uint4*>(sB_st + 8) = b1;
        }
        __syncthreads();

        #pragma unroll
        for (int ks = 0; ks < 2; ks++) {             // two k16 steps
            uint32_t af[4][4];
            uint32_t bf[2][4];
            #pragma unroll
            for (int bp = 0; bp < 2; bp++) {
                int r = wn * 32 + bp * 16 + bro;
                uint32_t off = (uint32_t)(r * TSTR + ks * 16 + bco) * 2;
                ldsm_x4(bf[bp], sB_b + off);
            }
            #pragma unroll
            for (int mt = 0; mt < 4; mt++) {
                int r = wm * 64 + mt * 16 + aro;
                uint32_t off = (uint32_t)(r * TSTR + ks * 16 + aco) * 2;
                ldsm_x4(af[mt], sA_b + off);
            }
            #pragma unroll
            for (int mt = 0; mt < 4; mt++)
                #pragma unroll
                for (int nt = 0; nt < 4; nt++)
                    mma_f16(acc[mt][nt], af[mt],
                            bf[nt >> 1][(nt & 1) * 2],
                            bf[nt >> 1][(nt & 1) * 2 + 1]);
        }
    }

    // ---- epilogue: store h as fp16 + fused fp32 score dots (proven) ---------
    const int hdl = wn >> 1;
    const int wp  = wn & 1;

    float alv[4][2], arv[4][2];
    #pragma unroll
    for (int nt = 0; nt < 4; nt++) {
        int col = bn + wn * 32 + nt * 8 + (lane & 3) * 2;
        alv[nt][0] = attn_l[col];     alv[nt][1] = attn_l[col + 1];
        arv[nt][0] = attn_r[col];     arv[nt][1] = attn_r[col + 1];
    }

    #pragma unroll
    for (int mt = 0; mt < 4; mt++) {
        int r0 = wm * 64 + mt * 16 + (lane >> 2);
        int r8 = r0 + 8;
        float sl0 = 0.f, sl8 = 0.f, sr0 = 0.f, sr8 = 0.f;
        #pragma unroll
        for (int nt = 0; nt < 4; nt++) {
            int col = bn + wn * 32 + nt * 8 + (lane & 3) * 2;
            float2 v0 = make_float2(acc[mt][nt][0], acc[mt][nt][1]);
            float2 v8 = make_float2(acc[mt][nt][2], acc[mt][nt][3]);
            __half2 p0 = __floats2half2_rn(v0.x, v0.y);
            __half2 p8 = __floats2half2_rn(v8.x, v8.y);
            *reinterpret_cast<__half2*>(&g_hh[(size_t)(bm + r0) * OUT_C + col]) = p0;
            *reinterpret_cast<__half2*>(&g_hh[(size_t)(bm + r8) * OUT_C + col]) = p8;
            sl0 += alv[nt][0] * v0.x + alv[nt][1] * v0.y;
            sl8 += alv[nt][0] * v8.x + alv[nt][1] * v8.y;
            sr0 += arv[nt][0] * v0.x + arv[nt][1] * v0.y;
            sr8 += arv[nt][0] * v8.x + arv[nt][1] * v8.y;
        }
        #pragma unroll
        for (int off = 1; off < 4; off <<= 1) {
            sl0 += __shfl_xor_sync(0xffffffffu, sl0, off);
            sl8 += __shfl_xor_sync(0xffffffffu, sl8, off);
            sr0 += __shfl_xor_sync(0xffffffffu, sr0, off);
            sr8 += __shfl_xor_sync(0xffffffffu, sr8, off);
        }
        if ((lane & 3) == 0) {
            s_sl[r0][hdl][wp] = sl0;  s_sl[r8][hdl][wp] = sl8;
            s_sr[r0][hdl][wp] = sr0;  s_sr[r8][hdl][wp] = sr8;
        }
    }
    __syncthreads();

    if (tid < 128) {
        int gr = bm + tid;
        int hb = bn >> 6;
        g_sl[(size_t)gr * 4 + hb + 0] = s_sl[tid][0][0] + s_sl[tid][0][1];
        g_sl[(size_t)gr * 4 + hb + 1] = s_sl[tid][1][0] + s_sl[tid][1][1];
        g_sr[(size_t)gr * 4 + hb + 0] = s_sr[tid][0][0] + s_sr[tid][0][1];
        g_sr[(size_t)gr * 4 + hb + 1] = s_sr[tid][1][0] + s_sr[tid][1][1];
    }
}

// ---------------------------------------------------------------------------
// Kernel D (round-11 proven, 112.3us config): softmax + fp16-gather agg.
// 64 threads per node, 4 nodes per block; thread t gathers 4 halves (LDG.64).
// ---------------------------------------------------------------------------
__global__ __launch_bounds__(256) void gat_agg_kernel(
    const int*    __restrict__ col_ind,
    const uint2*  __restrict__ hh2,
    const float4* __restrict__ sl4,
    const float4* __restrict__ sr4,
    float4*       __restrict__ out4)
{
    const int local = threadIdx.x >> 6;
    const int t     = threadIdx.x & 63;
    const int n     = blockIdx.x * 4 + local;

    __shared__ int   ssrc  [4][16];
    __shared__ float salpha[4][16][4];

    if (t < 16) {
        int s = col_ind[n * DEG + t];
        ssrc[local][t] = s;
        float4 l = sl4[n];
        float4 r = sr4[s];
        float e0 = l.x + r.x, e1 = l.y + r.y, e2 = l.z + r.z, e3 = l.w + r.w;
        e0 = (e0 > 0.f) ? e0 : NEG_SLOPE * e0;
        e1 = (e1 > 0.f) ? e1 : NEG_SLOPE * e1;
        e2 = (e2 > 0.f) ? e2 : NEG_SLOPE * e2;
        e3 = (e3 > 0.f) ? e3 : NEG_SLOPE * e3;
        float m0 = e0, m1 = e1, m2 = e2, m3 = e3;
        #pragma unroll
        for (int off = 8; off > 0; off >>= 1) {
            m0 = fmaxf(m0, __shfl_xor_sync(0xffffu, m0, off));
            m1 = fmaxf(m1, __shfl_xor_sync(0xffffu, m1, off));
            m2 = fmaxf(m2, __shfl_xor_sync(0xffffu, m2, off));
            m3 = fmaxf(m3, __shfl_xor_sync(0xffffu, m3, off));
        }
        float x0 = __expf(e0 - m0), x1 = __expf(e1 - m1);
        float x2 = __expf(e2 - m2), x3 = __expf(e3 - m3);
        float s0 = x0, s1 = x1, s2 = x2, s3 = x3;
        #pragma unroll
        for (int off = 8; off > 0; off >>= 1) {
            s0 += __shfl_xor_sync(0xffffu, s0, off);
            s1 += __shfl_xor_sync(0xffffu, s1, off);
            s2 += __shfl_xor_sync(0xffffu, s2, off);
            s3 += __shfl_xor_sync(0xffffu, s3, off);
        }
        *reinterpret_cast<float4*>(&salpha[local][t][0]) =
            make_float4(x0 / s0, x1 / s1, x2 / s2, x3 / s3);
    }
    __syncthreads();

    const int hd = t >> 4;
    float4 acc = make_float4(0.f, 0.f, 0.f, 0.f);
    #pragma unroll
    for (int k = 0; k < DEG; k++) {
        float a  = salpha[local][k][hd];
        uint2 u  = hh2[(size_t)ssrc[local][k] * 64 + t];
        float2 f01 = __half22float2(*reinterpret_cast<__half2*>(&u.x));
        float2 f23 = __half22float2(*reinterpret_cast<__half2*>(&u.y));
        acc.x += a * f01.x;
        acc.y += a * f01.y;
        acc.z += a * f23.x;
        acc.w += a * f23.y;
    }
    out4[(size_t)n * 64 + t] = acc;
}

// ---------------------------------------------------------------------------
// Launch. Inputs: row_ptr, col_ind, col_ptr, row_ind, feat, W, attn_l, attn_r
// ---------------------------------------------------------------------------
extern "C" void kernel_launch(void* const* d_in, const int* in_sizes, int n_in,
                              void* d_out, int out_size)
{
    const int*   col_ind = (const int*)  d_in[1];
    const float* feat    = (const float*)d_in[4];
    const float* W       = (const float*)d_in[5];
    const float* attn_l  = (const float*)d_in[6];
    const float* attn_r  = (const float*)d_in[7];
    float*       out     = (float*)      d_out;

    const int M = in_sizes[4] / IN_F;    // 50000

    __half* hh_ptr = nullptr;
    float  *sl_ptr = nullptr, *sr_ptr = nullptr;
    cudaGetSymbolAddress((void**)&hh_ptr, g_hh);
    cudaGetSymbolAddress((void**)&sl_ptr, g_sl);
    cudaGetSymbolAddress((void**)&sr_ptr, g_sr);

    dim3 gtw(IN_F / 32, OUT_C / 32);
    gat_transpose_w<<<gtw, 256>>>(W);

    dim3 gmm(N_PAD / 128, 2);
    gat_mma_kernel<<<gmm, 256>>>(feat, attn_l, attn_r, M);

    gat_agg_kernel<<<M / 4, 256>>>(col_ind,
                                   (const uint2*)hh_ptr,
                                   (const float4*)sl_ptr,
                                   (const float4*)sr_ptr,
                                   (float4*)out);
}

// round 16
// speedup vs baseline: 1.2474x; 1.0172x over previous
#include <cuda_runtime.h>
#include <cuda_bf16.h>
#include <cuda_fp16.h>
#include <cstdint>

#define N_NODES   50000
#define N_PAD     50048          // 782 * 64
#define DEG       16
#define IN_F      256
#define OUT_C     256            // NUM_HEADS * OUT_FEATS
#define NUM_HEADS 4
#define OUT_F     64
#define NEG_SLOPE 0.2f

// ---------------- scratch (static device globals; no allocation) ------------
__device__ __half g_wh[(size_t)OUT_C * IN_F];           // W^T [n][k], fp16
__device__ __half g_hh[(size_t)N_PAD * OUT_C];          // projected features (fp16)
__device__ float  g_sl[(size_t)N_PAD * NUM_HEADS];      // dst scores (fp32)
__device__ float  g_sr[(size_t)N_PAD * NUM_HEADS];      // src scores (fp32)

__device__ __forceinline__ uint32_t smem_u32(const void* p) {
    uint32_t a;
    asm("{ .reg .u64 t; cvta.to.shared.u64 t, %1; cvt.u32.u64 %0, t; }" : "=r"(a) : "l"(p));
    return a;
}

__device__ __forceinline__ void ldsm_x4(uint32_t* f, uint32_t addr) {
    asm volatile("ldmatrix.sync.aligned.m8n8.x4.shared.b16 {%0,%1,%2,%3}, [%4];"
                 : "=r"(f[0]), "=r"(f[1]), "=r"(f[2]), "=r"(f[3]) : "r"(addr));
}

__device__ __forceinline__ void mma_f16(float* c, const uint32_t* a,
                                        uint32_t b0, uint32_t b1) {
    asm volatile("mma.sync.aligned.m16n8k16.row.col.f32.f16.f16.f32 "
                 "{%0,%1,%2,%3}, {%4,%5,%6,%7}, {%8,%9}, {%0,%1,%2,%3};"
                 : "+f"(c[0]), "+f"(c[1]), "+f"(c[2]), "+f"(c[3])
                 : "r"(a[0]), "r"(a[1]), "r"(a[2]), "r"(a[3]), "r"(b0), "r"(b1));
}

__device__ __forceinline__ uint32_t pk2h(float x, float y) {
    __half2 h = __floats2half2_rn(x, y);
    return *reinterpret_cast<uint32_t*>(&h);
}

// ---------------------------------------------------------------------------
// Kernel B: transpose W [k][n] -> g_wh [n][k], fp16 (~4us)
// ---------------------------------------------------------------------------
__global__ __launch_bounds__(256) void gat_transpose_w(const float* __restrict__ W)
{
    __shared__ float tile[32][33];
    const int bk = blockIdx.x * 32;
    const int bn = blockIdx.y * 32;
    const int tx = threadIdx.x & 31;
    const int ty = threadIdx.x >> 5;
    #pragma unroll
    for (int j = 0; j < 32; j += 8)
        tile[ty + j][tx] = W[(size_t)(bk + ty + j) * OUT_C + bn + tx];
    __syncthreads();
    #pragma unroll
    for (int j = 0; j < 32; j += 8)
        g_wh[(size_t)(bn + ty + j) * IN_F + bk + tx] = __float2half_rn(tile[tx][ty + j]);
}

// ---------------------------------------------------------------------------
// Kernel C: single-pass FP16 mma.sync GEMM h = feat @ W, fp32 accum.
// CTA = 64(M) x 256(N), 256 threads, 8 warps 1(m) x 8(n); warp tile is the
// PROVEN 64x32 (round-15 fragment layout verbatim, wm fixed to 0).
// A (feat) is read from DRAM EXACTLY ONCE (782 CTAs x disjoint 64-row strips);
// B (g_wh, 128KB) is L2-resident so its 2x read amplification is cheap.
// Smem ~30KB -> 2 CTAs/SM preserved. Epilogue: full 256-col rows -> fp16 h
// + fused fp32 attn score dots for all 4 heads.
// ---------------------------------------------------------------------------
#define TSTR 40   // smem row stride in fp16 elems (80B) -> conflict-free ldsm

__global__ __launch_bounds__(256, 2) void gat_mma_kernel(
    const float* __restrict__ feat,
    const float* __restrict__ attn_l,
    const float* __restrict__ attn_r,
    int M)
{
    __shared__ __align__(16) __half sA[64 * TSTR];     // 5 KB
    __shared__ __align__(16) __half sB[256 * TSTR];    // 20 KB
    __shared__ float s_sl[64][4][2];                   // [row][head][warp-pair]
    __shared__ float s_sr[64][4][2];

    const int tid  = threadIdx.x;
    const int wid  = tid >> 5;
    const int lane = tid & 31;
    const int bm   = blockIdx.x * 64;
    const int wn   = wid;                              // 0..7

    const uint32_t sA_b = smem_u32(sA);
    const uint32_t sB_b = smem_u32(sB);

    float acc[4][4][4];
    #pragma unroll
    for (int mt = 0; mt < 4; mt++)
        #pragma unroll
        for (int nt = 0; nt < 4; nt++)
            #pragma unroll
            for (int r = 0; r < 4; r++) acc[mt][nt][r] = 0.f;

    // A loader: 64 rows x 32 f32; 4 threads per row, 8 f32 each
    const int arow = tid >> 2;
    const int acol = (tid & 3) * 8;
    const bool arow_ok = (bm + arow) < M;
    const float* aptr = feat + (size_t)(bm + arow) * IN_F + acol;
    __half* const sA_st = sA + arow * TSTR + acol;

    // B loader: 256 rows x 32 halves; 2 iterations of 128 rows, 16 halves/thread
    const int brow = tid >> 1;
    const int bcol = (tid & 1) * 16;
    const __half* bptr = g_wh + (size_t)brow * IN_F + bcol;
    __half* const sB_st = sB + brow * TSTR + bcol;

    // ldmatrix lane-address components (proven b16 layout)
    const int mi  = lane >> 3;
    const int aro = ((mi & 1) << 3) + (lane & 7);
    const int aco = (mi >> 1) << 3;
    const int bro = ((mi >> 1) << 3) + (lane & 7);
    const int bco = (mi & 1) << 3;

    for (int c = 0; c < 8; c++) {                      // k-chunks of 32
        __syncthreads();
        {
            float4 a0, a1;
            if (arow_ok) {
                a0 = *reinterpret_cast<const float4*>(aptr + c * 32);
                a1 = *reinterpret_cast<const float4*>(aptr + c * 32 + 4);
            } else {
                a0 = a1 = make_float4(0.f, 0.f, 0.f, 0.f);
            }
            *reinterpret_cast<uint4*>(sA_st) =
                make_uint4(pk2h(a0.x, a0.y), pk2h(a0.z, a0.w),
                           pk2h(a1.x, a1.y), pk2h(a1.z, a1.w));
            #pragma unroll
            for (int i = 0; i < 2; i++) {
                uint4 b0 = *reinterpret_cast<const uint4*>(bptr + (size_t)i * 128 * IN_F + c * 32);
                uint4 b1 = *reinterpret_cast<const uint4*>(bptr + (size_t)i * 128 * IN_F + c * 32 + 8);
                *reinterpret_cast<uint4*>(sB_st + i * 128 * TSTR)     = b0;
                *reinterpret_cast<uint4*>(sB_st + i * 128 * TSTR + 8) = b1;
            }
        }
        __syncthreads();

        #pragma unroll
        for (int ks = 0; ks < 2; ks++) {               // two k16 steps
            uint32_t af[4][4];
            uint32_t bf[2][4];
            #pragma unroll
            for (int bp = 0; bp < 2; bp++) {
                int r = wn * 32 + bp * 16 + bro;
                uint32_t off = (uint32_t)(r * TSTR + ks * 16 + bco) * 2;
                ldsm_x4(bf[bp], sB_b + off);
            }
            #pragma unroll
            for (int mt = 0; mt < 4; mt++) {
                int r = mt * 16 + aro;
                uint32_t off = (uint32_t)(r * TSTR + ks * 16 + aco) * 2;
                ldsm_x4(af[mt], sA_b + off);
            }
            #pragma unroll
            for (int mt = 0; mt < 4; mt++)
                #pragma unroll
                for (int nt = 0; nt < 4; nt++)
                    mma_f16(acc[mt][nt], af[mt],
                            bf[nt >> 1][(nt & 1) * 2],
                            bf[nt >> 1][(nt & 1) * 2 + 1]);
        }
    }

    // ---- epilogue: store h as fp16 + fused fp32 score dots ------------------
    const int hdl = wn >> 1;               // head 0..3
    const int wp  = wn & 1;                // warp-pair slot

    float alv[4][2], arv[4][2];
    #pragma unroll
    for (int nt = 0; nt < 4; nt++) {
        int col = wn * 32 + nt * 8 + (lane & 3) * 2;
        alv[nt][0] = attn_l[col];     alv[nt][1] = attn_l[col + 1];
        arv[nt][0] = attn_r[col];     arv[nt][1] = attn_r[col + 1];
    }

    #pragma unroll
    for (int mt = 0; mt < 4; mt++) {
        int r0 = mt * 16 + (lane >> 2);
        int r8 = r0 + 8;
        float sl0 = 0.f, sl8 = 0.f, sr0 = 0.f, sr8 = 0.f;
        #pragma unroll
        for (int nt = 0; nt < 4; nt++) {
            int col = wn * 32 + nt * 8 + (lane & 3) * 2;
            float2 v0 = make_float2(acc[mt][nt][0], acc[mt][nt][1]);
            float2 v8 = make_float2(acc[mt][nt][2], acc[mt][nt][3]);
            __half2 p0 = __floats2half2_rn(v0.x, v0.y);
            __half2 p8 = __floats2half2_rn(v8.x, v8.y);
            *reinterpret_cast<__half2*>(&g_hh[(size_t)(bm + r0) * OUT_C + col]) = p0;
            *reinterpret_cast<__half2*>(&g_hh[(size_t)(bm + r8) * OUT_C + col]) = p8;
            sl0 += alv[nt][0] * v0.x + alv[nt][1] * v0.y;
            sl8 += alv[nt][0] * v8.x + alv[nt][1] * v8.y;
            sr0 += arv[nt][0] * v0.x + arv[nt][1] * v0.y;
            sr8 += arv[nt][0] * v8.x + arv[nt][1] * v8.y;
        }
        #pragma unroll
        for (int off = 1; off < 4; off <<= 1) {
            sl0 += __shfl_xor_sync(0xffffffffu, sl0, off);
            sl8 += __shfl_xor_sync(0xffffffffu, sl8, off);
            sr0 += __shfl_xor_sync(0xffffffffu, sr0, off);
            sr8 += __shfl_xor_sync(0xffffffffu, sr8, off);
        }
        if ((lane & 3) == 0) {
            s_sl[r0][hdl][wp] = sl0;  s_sl[r8][hdl][wp] = sl8;
            s_sr[r0][hdl][wp] = sr0;  s_sr[r8][hdl][wp] = sr8;
        }
    }
    __syncthreads();

    if (tid < 64) {
        int gr = bm + tid;
        float4 l = make_float4(s_sl[tid][0][0] + s_sl[tid][0][1],
                               s_sl[tid][1][0] + s_sl[tid][1][1],
                               s_sl[tid][2][0] + s_sl[tid][2][1],
                               s_sl[tid][3][0] + s_sl[tid][3][1]);
        float4 r = make_float4(s_sr[tid][0][0] + s_sr[tid][0][1],
                               s_sr[tid][1][0] + s_sr[tid][1][1],
                               s_sr[tid][2][0] + s_sr[tid][2][1],
                               s_sr[tid][3][0] + s_sr[tid][3][1]);
        *reinterpret_cast<float4*>(&g_sl[(size_t)gr * 4]) = l;
        *reinterpret_cast<float4*>(&g_sr[(size_t)gr * 4]) = r;
    }
}

// ---------------------------------------------------------------------------
// Kernel D (proven, 98.7us config): softmax + fp16-gather aggregation.
// 64 threads per node, 4 nodes per block; thread t gathers 4 halves (LDG.64).
// ---------------------------------------------------------------------------
__global__ __launch_bounds__(256) void gat_agg_kernel(
    const int*    __restrict__ col_ind,
    const uint2*  __restrict__ hh2,
    const float4* __restrict__ sl4,
    const float4* __restrict__ sr4,
    float4*       __restrict__ out4)
{
    const int local = threadIdx.x >> 6;
    const int t     = threadIdx.x & 63;
    const int n     = blockIdx.x * 4 + local;

    __shared__ int   ssrc  [4][16];
    __shared__ float salpha[4][16][4];

    if (t < 16) {
        int s = col_ind[n * DEG + t];
        ssrc[local][t] = s;
        float4 l = sl4[n];
        float4 r = sr4[s];
        float e0 = l.x + r.x, e1 = l.y + r.y, e2 = l.z + r.z, e3 = l.w + r.w;
        e0 = (e0 > 0.f) ? e0 : NEG_SLOPE * e0;
        e1 = (e1 > 0.f) ? e1 : NEG_SLOPE * e1;
        e2 = (e2 > 0.f) ? e2 : NEG_SLOPE * e2;
        e3 = (e3 > 0.f) ? e3 : NEG_SLOPE * e3;
        float m0 = e0, m1 = e1, m2 = e2, m3 = e3;
        #pragma unroll
        for (int off = 8; off > 0; off >>= 1) {
            m0 = fmaxf(m0, __shfl_xor_sync(0xffffu, m0, off));
            m1 = fmaxf(m1, __shfl_xor_sync(0xffffu, m1, off));
            m2 = fmaxf(m2, __shfl_xor_sync(0xffffu, m2, off));
            m3 = fmaxf(m3, __shfl_xor_sync(0xffffu, m3, off));
        }
        float x0 = __expf(e0 - m0), x1 = __expf(e1 - m1);
        float x2 = __expf(e2 - m2), x3 = __expf(e3 - m3);
        float s0 = x0, s1 = x1, s2 = x2, s3 = x3;
        #pragma unroll
        for (int off = 8; off > 0; off >>= 1) {
            s0 += __shfl_xor_sync(0xffffu, s0, off);
            s1 += __shfl_xor_sync(0xffffu, s1, off);
            s2 += __shfl_xor_sync(0xffffu, s2, off);
            s3 += __shfl_xor_sync(0xffffu, s3, off);
        }
        *reinterpret_cast<float4*>(&salpha[local][t][0]) =
            make_float4(x0 / s0, x1 / s1, x2 / s2, x3 / s3);
    }
    __syncthreads();

    const int hd = t >> 4;
    float4 acc = make_float4(0.f, 0.f, 0.f, 0.f);
    #pragma unroll
    for (int k = 0; k < DEG; k++) {
        float a  = salpha[local][k][hd];
        uint2 u  = hh2[(size_t)ssrc[local][k] * 64 + t];
        float2 f01 = __half22float2(*reinterpret_cast<__half2*>(&u.x));
        float2 f23 = __half22float2(*reinterpret_cast<__half2*>(&u.y));
        acc.x += a * f01.x;
        acc.y += a * f01.y;
        acc.z += a * f23.x;
        acc.w += a * f23.y;
    }
    out4[(size_t)n * 64 + t] = acc;
}

// ---------------------------------------------------------------------------
// Launch. Inputs: row_ptr, col_ind, col_ptr, row_ind, feat, W, attn_l, attn_r
// ---------------------------------------------------------------------------
extern "C" void kernel_launch(void* const* d_in, const int* in_sizes, int n_in,
                              void* d_out, int out_size)
{
    const int*   col_ind = (const int*)  d_in[1];
    const float* feat    = (const float*)d_in[4];
    const float* W       = (const float*)d_in[5];
    const float* attn_l  = (const float*)d_in[6];
    const float* attn_r  = (const float*)d_in[7];
    float*       out     = (float*)      d_out;

    const int M = in_sizes[4] / IN_F;    // 50000

    __half* hh_ptr = nullptr;
    float  *sl_ptr = nullptr, *sr_ptr = nullptr;
    cudaGetSymbolAddress((void**)&hh_ptr, g_hh);
    cudaGetSymbolAddress((void**)&sl_ptr, g_sl);
    cudaGetSymbolAddress((void**)&sr_ptr, g_sr);

    dim3 gtw(IN_F / 32, OUT_C / 32);
    gat_transpose_w<<<gtw, 256>>>(W);

    gat_mma_kernel<<<N_PAD / 64, 256>>>(feat, attn_l, attn_r, M);

    gat_agg_kernel<<<M / 4, 256>>>(col_ind,
                                   (const uint2*)hh_ptr,
                                   (const float4*)sl_ptr,
                                   (const float4*)sr_ptr,
                                   (float4*)out);
}

// round 17
// speedup vs baseline: 1.3097x; 1.0499x over previous
#include <cuda_runtime.h>
#include <cuda_bf16.h>
#include <cuda_fp16.h>
#include <cstdint>

#define N_NODES   50000
#define N_PAD     50048          // 782 * 64
#define DEG       16
#define IN_F      256
#define OUT_C     256            // NUM_HEADS * OUT_FEATS
#define NUM_HEADS 4
#define OUT_F     64
#define NEG_SLOPE 0.2f

// ---------------- scratch (static device globals; no allocation) ------------
__device__ __half g_wh[(size_t)OUT_C * IN_F];           // W^T [n][k], fp16
__device__ __half g_hh[(size_t)N_PAD * OUT_C];          // projected features (fp16)
__device__ float  g_sl[(size_t)N_PAD * NUM_HEADS];      // dst scores (fp32)
__device__ float  g_sr[(size_t)N_PAD * NUM_HEADS];      // src scores (fp32)

__device__ __forceinline__ uint32_t smem_u32(const void* p) {
    uint32_t a;
    asm("{ .reg .u64 t; cvta.to.shared.u64 t, %1; cvt.u32.u64 %0, t; }" : "=r"(a) : "l"(p));
    return a;
}

__device__ __forceinline__ void ldsm_x4(uint32_t* f, uint32_t addr) {
    asm volatile("ldmatrix.sync.aligned.m8n8.x4.shared.b16 {%0,%1,%2,%3}, [%4];"
                 : "=r"(f[0]), "=r"(f[1]), "=r"(f[2]), "=r"(f[3]) : "r"(addr));
}

__device__ __forceinline__ void mma_f16(float* c, const uint32_t* a,
                                        uint32_t b0, uint32_t b1) {
    asm volatile("mma.sync.aligned.m16n8k16.row.col.f32.f16.f16.f32 "
                 "{%0,%1,%2,%3}, {%4,%5,%6,%7}, {%8,%9}, {%0,%1,%2,%3};"
                 : "+f"(c[0]), "+f"(c[1]), "+f"(c[2]), "+f"(c[3])
                 : "r"(a[0]), "r"(a[1]), "r"(a[2]), "r"(a[3]), "r"(b0), "r"(b1));
}

__device__ __forceinline__ uint32_t pk2h(float x, float y) {
    __half2 h = __floats2half2_rn(x, y);
    return *reinterpret_cast<uint32_t*>(&h);
}

// ---------------------------------------------------------------------------
// Kernel B: transpose W [k][n] -> g_wh [n][k], fp16 (~4us)
// ---------------------------------------------------------------------------
__global__ __launch_bounds__(256) void gat_transpose_w(const float* __restrict__ W)
{
    __shared__ float tile[32][33];
    const int bk = blockIdx.x * 32;
    const int bn = blockIdx.y * 32;
    const int tx = threadIdx.x & 31;
    const int ty = threadIdx.x >> 5;
    #pragma unroll
    for (int j = 0; j < 32; j += 8)
        tile[ty + j][tx] = W[(size_t)(bk + ty + j) * OUT_C + bn + tx];
    __syncthreads();
    #pragma unroll
    for (int j = 0; j < 32; j += 8)
        g_wh[(size_t)(bn + ty + j) * IN_F + bk + tx] = __float2half_rn(tile[tx][ty + j]);
}

// ---------------------------------------------------------------------------
// Kernel C: single-pass FP16 mma.sync GEMM h = feat @ W, fp32 accum.
// Round-16 proven shape: CTA = 64(M) x 256(N), 256 threads, 8 warps 1x8,
// warp tile 64x32, 2 CTAs/SM. NEW: register prefetch of chunk c+1 (24 regs,
// fits the 128-reg budget at this shape) so global loads overlap the MMA
// section; single smem buffer.
// Epilogue: h stored FP16 + fused fp32 attn score dots (proven verbatim).
// ---------------------------------------------------------------------------
#define TSTR 40   // smem row stride in fp16 elems (80B) -> conflict-free ldsm

__global__ __launch_bounds__(256, 2) void gat_mma_kernel(
    const float* __restrict__ feat,
    const float* __restrict__ attn_l,
    const float* __restrict__ attn_r,
    int M)
{
    __shared__ __align__(16) __half sA[64 * TSTR];     // 5 KB
    __shared__ __align__(16) __half sB[256 * TSTR];    // 20 KB
    __shared__ float s_sl[64][4][2];
    __shared__ float s_sr[64][4][2];

    const int tid  = threadIdx.x;
    const int wid  = tid >> 5;
    const int lane = tid & 31;
    const int bm   = blockIdx.x * 64;
    const int wn   = wid;                              // 0..7

    const uint32_t sA_b = smem_u32(sA);
    const uint32_t sB_b = smem_u32(sB);

    float acc[4][4][4];
    #pragma unroll
    for (int mt = 0; mt < 4; mt++)
        #pragma unroll
        for (int nt = 0; nt < 4; nt++)
            #pragma unroll
            for (int r = 0; r < 4; r++) acc[mt][nt][r] = 0.f;

    // A loader: 64 rows x 32 f32; 4 threads per row, 8 f32 each
    const int arow = tid >> 2;
    const int acol = (tid & 3) * 8;
    const bool arow_ok = (bm + arow) < M;
    const float* aptr = feat + (size_t)(bm + arow) * IN_F + acol;
    __half* const sA_st = sA + arow * TSTR + acol;

    // B loader: 256 rows x 32 halves; 2 groups of 128 rows, 16 halves/thread
    const int brow = tid >> 1;
    const int bcol = (tid & 1) * 16;
    const __half* bptr = g_wh + (size_t)brow * IN_F + bcol;
    __half* const sB_st = sB + brow * TSTR + bcol;

    // ldmatrix lane-address components (proven b16 layout)
    const int mi  = lane >> 3;
    const int aro = ((mi & 1) << 3) + (lane & 7);
    const int aco = (mi >> 1) << 3;
    const int bro = ((mi >> 1) << 3) + (lane & 7);
    const int bco = (mi & 1) << 3;

    // ---- prologue: load chunk 0 into registers -----------------------------
    float4 pa0, pa1;
    uint4  pb00, pb01, pb10, pb11;
    if (arow_ok) {
        pa0 = *reinterpret_cast<const float4*>(aptr);
        pa1 = *reinterpret_cast<const float4*>(aptr + 4);
    } else {
        pa0 = pa1 = make_float4(0.f, 0.f, 0.f, 0.f);
    }
    pb00 = *reinterpret_cast<const uint4*>(bptr);
    pb01 = *reinterpret_cast<const uint4*>(bptr + 8);
    pb10 = *reinterpret_cast<const uint4*>(bptr + (size_t)128 * IN_F);
    pb11 = *reinterpret_cast<const uint4*>(bptr + (size_t)128 * IN_F + 8);

    for (int c = 0; c < 8; c++) {                      // k-chunks of 32
        __syncthreads();
        // store prefetched chunk c into smem
        *reinterpret_cast<uint4*>(sA_st) =
            make_uint4(pk2h(pa0.x, pa0.y), pk2h(pa0.z, pa0.w),
                       pk2h(pa1.x, pa1.y), pk2h(pa1.z, pa1.w));
        *reinterpret_cast<uint4*>(sB_st)                  = pb00;
        *reinterpret_cast<uint4*>(sB_st + 8)              = pb01;
        *reinterpret_cast<uint4*>(sB_st + 128 * TSTR)     = pb10;
        *reinterpret_cast<uint4*>(sB_st + 128 * TSTR + 8) = pb11;
        __syncthreads();

        // issue loads for chunk c+1 (consumed next iteration, overlap MMA)
        if (c < 7) {
            const int ko = (c + 1) * 32;
            if (arow_ok) {
                pa0 = *reinterpret_cast<const float4*>(aptr + ko);
                pa1 = *reinterpret_cast<const float4*>(aptr + ko + 4);
            }
            pb00 = *reinterpret_cast<const uint4*>(bptr + ko);
            pb01 = *reinterpret_cast<const uint4*>(bptr + ko + 8);
            pb10 = *reinterpret_cast<const uint4*>(bptr + (size_t)128 * IN_F + ko);
            pb11 = *reinterpret_cast<const uint4*>(bptr + (size_t)128 * IN_F + ko + 8);
        }

        #pragma unroll
        for (int ks = 0; ks < 2; ks++) {               // two k16 steps
            uint32_t af[4][4];
            uint32_t bf[2][4];
            #pragma unroll
            for (int bp = 0; bp < 2; bp++) {
                int r = wn * 32 + bp * 16 + bro;
                uint32_t off = (uint32_t)(r * TSTR + ks * 16 + bco) * 2;
                ldsm_x4(bf[bp], sB_b + off);
            }
            #pragma unroll
            for (int mt = 0; mt < 4; mt++) {
                int r = mt * 16 + aro;
                uint32_t off = (uint32_t)(r * TSTR + ks * 16 + aco) * 2;
                ldsm_x4(af[mt], sA_b + off);
            }
            #pragma unroll
            for (int mt = 0; mt < 4; mt++)
                #pragma unroll
                for (int nt = 0; nt < 4; nt++)
                    mma_f16(acc[mt][nt], af[mt],
                            bf[nt >> 1][(nt & 1) * 2],
                            bf[nt >> 1][(nt & 1) * 2 + 1]);
        }
    }

    // ---- epilogue: store h as fp16 + fused fp32 score dots ------------------
    const int hdl = wn >> 1;               // head 0..3
    const int wp  = wn & 1;                // warp-pair slot

    float alv[4][2], arv[4][2];
    #pragma unroll
    for (int nt = 0; nt < 4; nt++) {
        int col = wn * 32 + nt * 8 + (lane & 3) * 2;
        alv[nt][0] = attn_l[col];     alv[nt][1] = attn_l[col + 1];
        arv[nt][0] = attn_r[col];     arv[nt][1] = attn_r[col + 1];
    }

    #pragma unroll
    for (int mt = 0; mt < 4; mt++) {
        int r0 = mt * 16 + (lane >> 2);
        int r8 = r0 + 8;
        float sl0 = 0.f, sl8 = 0.f, sr0 = 0.f, sr8 = 0.f;
        #pragma unroll
        for (int nt = 0; nt < 4; nt++) {
            int col = wn * 32 + nt * 8 + (lane & 3) * 2;
            float2 v0 = make_float2(acc[mt][nt][0], acc[mt][nt][1]);
            float2 v8 = make_float2(acc[mt][nt][2], acc[mt][nt][3]);
            __half2 p0 = __floats2half2_rn(v0.x, v0.y);
            __half2 p8 = __floats2half2_rn(v8.x, v8.y);
            *reinterpret_cast<__half2*>(&g_hh[(size_t)(bm + r0) * OUT_C + col]) = p0;
            *reinterpret_cast<__half2*>(&g_hh[(size_t)(bm + r8) * OUT_C + col]) = p8;
            sl0 += alv[nt][0] * v0.x + alv[nt][1] * v0.y;
            sl8 += alv[nt][0] * v8.x + alv[nt][1] * v8.y;
            sr0 += arv[nt][0] * v0.x + arv[nt][1] * v0.y;
            sr8 += arv[nt][0] * v8.x + arv[nt][1] * v8.y;
        }
        #pragma unroll
        for (int off = 1; off < 4; off <<= 1) {
            sl0 += __shfl_xor_sync(0xffffffffu, sl0, off);
            sl8 += __shfl_xor_sync(0xffffffffu, sl8, off);
            sr0 += __shfl_xor_sync(0xffffffffu, sr0, off);
            sr8 += __shfl_xor_sync(0xffffffffu, sr8, off);
        }
        if ((lane & 3) == 0) {
            s_sl[r0][hdl][wp] = sl0;  s_sl[r8][hdl][wp] = sl8;
            s_sr[r0][hdl][wp] = sr0;  s_sr[r8][hdl][wp] = sr8;
        }
    }
    __syncthreads();

    if (tid < 64) {
        int gr = bm + tid;
        float4 l = make_float4(s_sl[tid][0][0] + s_sl[tid][0][1],
                               s_sl[tid][1][0] + s_sl[tid][1][1],
                               s_sl[tid][2][0] + s_sl[tid][2][1],
                               s_sl[tid][3][0] + s_sl[tid][3][1]);
        float4 r = make_float4(s_sr[tid][0][0] + s_sr[tid][0][1],
                               s_sr[tid][1][0] + s_sr[tid][1][1],
                               s_sr[tid][2][0] + s_sr[tid][2][1],
                               s_sr[tid][3][0] + s_sr[tid][3][1]);
        *reinterpret_cast<float4*>(&g_sl[(size_t)gr * 4]) = l;
        *reinterpret_cast<float4*>(&g_sr[(size_t)gr * 4]) = r;
    }
}

// ---------------------------------------------------------------------------
// Kernel D (proven): softmax + fp16-gather aggregation.
// 64 threads per node, 4 nodes per block; thread t gathers 4 halves (LDG.64).
// ---------------------------------------------------------------------------
__global__ __launch_bounds__(256) void gat_agg_kernel(
    const int*    __restrict__ col_ind,
    const uint2*  __restrict__ hh2,
    const float4* __restrict__ sl4,
    const float4* __restrict__ sr4,
    float4*       __restrict__ out4)
{
    const int local = threadIdx.x >> 6;
    const int t     = threadIdx.x & 63;
    const int n     = blockIdx.x * 4 + local;

    __shared__ int   ssrc  [4][16];
    __shared__ float salpha[4][16][4];

    if (t < 16) {
        int s = col_ind[n * DEG + t];
        ssrc[local][t] = s;
        float4 l = sl4[n];
        float4 r = sr4[s];
        float e0 = l.x + r.x, e1 = l.y + r.y, e2 = l.z + r.z, e3 = l.w + r.w;
        e0 = (e0 > 0.f) ? e0 : NEG_SLOPE * e0;
        e1 = (e1 > 0.f) ? e1 : NEG_SLOPE * e1;
        e2 = (e2 > 0.f) ? e2 : NEG_SLOPE * e2;
        e3 = (e3 > 0.f) ? e3 : NEG_SLOPE * e3;
        float m0 = e0, m1 = e1, m2 = e2, m3 = e3;
        #pragma unroll
        for (int off = 8; off > 0; off >>= 1) {
            m0 = fmaxf(m0, __shfl_xor_sync(0xffffu, m0, off));
            m1 = fmaxf(m1, __shfl_xor_sync(0xffffu, m1, off));
            m2 = fmaxf(m2, __shfl_xor_sync(0xffffu, m2, off));
            m3 = fmaxf(m3, __shfl_xor_sync(0xffffu, m3, off));
        }
        float x0 = __expf(e0 - m0), x1 = __expf(e1 - m1);
        float x2 = __expf(e2 - m2), x3 = __expf(e3 - m3);
        float s0 = x0, s1 = x1, s2 = x2, s3 = x3;
        #pragma unroll
        for (int off = 8; off > 0; off >>= 1) {
            s0 += __shfl_xor_sync(0xffffu, s0, off);
            s1 += __shfl_xor_sync(0xffffu, s1, off);
            s2 += __shfl_xor_sync(0xffffu, s2, off);
            s3 += __shfl_xor_sync(0xffffu, s3, off);
        }
        *reinterpret_cast<float4*>(&salpha[local][t][0]) =
            make_float4(x0 / s0, x1 / s1, x2 / s2, x3 / s3);
    }
    __syncthreads();

    const int hd = t >> 4;
    float4 acc = make_float4(0.f, 0.f, 0.f, 0.f);
    #pragma unroll
    for (int k = 0; k < DEG; k++) {
        float a  = salpha[local][k][hd];
        uint2 u  = hh2[(size_t)ssrc[local][k] * 64 + t];
        float2 f01 = __half22float2(*reinterpret_cast<__half2*>(&u.x));
        float2 f23 = __half22float2(*reinterpret_cast<__half2*>(&u.y));
        acc.x += a * f01.x;
        acc.y += a * f01.y;
        acc.z += a * f23.x;
        acc.w += a * f23.y;
    }
    out4[(size_t)n * 64 + t] = acc;
}

// ---------------------------------------------------------------------------
// Launch. Inputs: row_ptr, col_ind, col_ptr, row_ind, feat, W, attn_l, attn_r
// ---------------------------------------------------------------------------
extern "C" void kernel_launch(void* const* d_in, const int* in_sizes, int n_in,
                              void* d_out, int out_size)
{
    const int*   col_ind = (const int*)  d_in[1];
    const float* feat    = (const float*)d_in[4];
    const float* W       = (const float*)d_in[5];
    const float* attn_l  = (const float*)d_in[6];
    const float* attn_r  = (const float*)d_in[7];
    float*       out     = (float*)      d_out;

    const int M = in_sizes[4] / IN_F;    // 50000

    __half* hh_ptr = nullptr;
    float  *sl_ptr = nullptr, *sr_ptr = nullptr;
    cudaGetSymbolAddress((void**)&hh_ptr, g_hh);
    cudaGetSymbolAddress((void**)&sl_ptr, g_sl);
    cudaGetSymbolAddress((void**)&sr_ptr, g_sr);

    dim3 gtw(IN_F / 32, OUT_C / 32);
    gat_transpose_w<<<gtw, 256>>>(W);

    gat_mma_kernel<<<N_PAD / 64, 256>>>(feat, attn_l, attn_r, M);

    gat_agg_kernel<<<M / 4, 256>>>(col_ind,
                                   (const uint2*)hh_ptr,
                                   (const float4*)sl_ptr,
                                   (const float4*)sr_ptr,
                                   (float4*)out);
}